// round 8
// baseline (speedup 1.0000x reference)
#include <cuda_runtime.h>
#include <cstdint>

#define DEV_INLINE __device__ __forceinline__

constexpr int Bn = 1024, Tn = 128, In = 128, Hn = 1024, G4 = 4096, On = 64;
constexpr int K_TOT = In + Hn;          // 1152
constexpr int KC = 32;                  // K floats per chunk
constexpr int NCHUNK = K_TOT / KC;      // 36
constexpr int MT = 128;                 // M tile
constexpr int HT = 32;                  // h-cols per CTA (N tile = 4 gates x 32 = 128)
constexpr int SPAD = 36;                // padded row stride (floats), conflict-free LDS
constexpr int NSTAGE = 3;

// ping-pong hidden state: step t reads g_hbuf[t&1], writes g_hbuf[(t&1)^1]
__device__ float g_h0[Bn * Hn];
__device__ float g_h1[Bn * Hn];
__device__ float g_c[Bn * Hn];
__device__ float g_w[G4 * K_TOT];       // [w_ih | w_hh], tf32-rounded
__device__ float g_x[Bn * Tn * In];     // tf32-rounded x

constexpr int SM_STG0 = 1024;                         // bias in [0,512), pad to 1KB
constexpr int HALF_BYTES = MT * SPAD * 4;             // 18432
constexpr int STG_BYTES = 2 * HALF_BYTES;             // 36864
constexpr int SMEM_BYTES = SM_STG0 + NSTAGE * STG_BYTES;   // 111616

#define CPA16(dst, src) asm volatile("cp.async.cg.shared.global [%0], [%1], 16;" :: "r"(dst), "l"(src))
#define CP_COMMIT()     asm volatile("cp.async.commit_group;" ::: "memory")
#define CP_WAIT_2()     asm volatile("cp.async.wait_group 2;" ::: "memory")
#define CP_WAIT_1()     asm volatile("cp.async.wait_group 1;" ::: "memory")
#define CP_WAIT_0()     asm volatile("cp.async.wait_group 0;" ::: "memory")

DEV_INLINE uint32_t smem_u32(const void* p) {
    uint32_t a;
    asm("{ .reg .u64 t; cvta.to.shared.u64 t, %1; cvt.u32.u64 %0, t; }" : "=r"(a) : "l"(p));
    return a;
}

DEV_INLINE void mma8(float* c, const uint32_t* a, const uint32_t* b) {
    asm volatile(
        "mma.sync.aligned.m16n8k8.row.col.f32.tf32.tf32.f32 "
        "{%0,%1,%2,%3}, {%4,%5,%6,%7}, {%8,%9}, {%0,%1,%2,%3};"
        : "+f"(c[0]), "+f"(c[1]), "+f"(c[2]), "+f"(c[3])
        : "r"(a[0]), "r"(a[1]), "r"(a[2]), "r"(a[3]), "r"(b[0]), "r"(b[1]));
}

DEV_INLINE float sigf(float x) {
    float e, r;
    asm("ex2.approx.f32 %0, %1;" : "=f"(e) : "f"(-1.4426950408889634f * x));
    asm("rcp.approx.f32 %0, %1;" : "=f"(r) : "f"(1.0f + e));
    return r;
}
DEV_INLINE float tanhf_(float x) { return 2.0f * sigf(2.0f * x) - 1.0f; }
DEV_INLINE float tf32r(float x) {
    uint32_t u;
    asm("cvt.rna.tf32.f32 %0, %1;" : "=r"(u) : "f"(x));
    return __uint_as_float(u);
}

// ---------------- prep ----------------
__global__ void init_hc_kernel() {
    int i = blockIdx.x * blockDim.x + threadIdx.x;
    if (i < Bn * Hn) { g_h0[i] = 0.0f; g_h1[i] = 0.0f; g_c[i] = 0.0f; }
}
__global__ void prep_w_kernel(const float* __restrict__ w_ih, const float* __restrict__ w_hh) {
    int i = blockIdx.x * blockDim.x + threadIdx.x;
    if (i >= G4 * K_TOT) return;
    int n = i / K_TOT, k = i - n * K_TOT;
    g_w[i] = tf32r(k < In ? w_ih[n * In + k] : w_hh[n * Hn + (k - In)]);
}
__global__ void prep_x_kernel(const float* __restrict__ x) {
    int i = blockIdx.x * blockDim.x + threadIdx.x;
    if (i < Bn * Tn * In) g_x[i] = tf32r(x[i]);
}

// ---------------- chunk loader ----------------
DEV_INLINE void load_chunk(int kc, int m0, int nbase, uint32_t sA, uint32_t sB,
                           int t, int tid, const float* __restrict__ hin) {
    int k0 = kc * KC;
    const float* abase;
    int apitch;
    if (k0 < In) { abase = g_x + (size_t)m0 * (Tn * In) + t * In + k0; apitch = Tn * In; }
    else         { abase = hin + (size_t)m0 * Hn + (k0 - In);          apitch = Hn; }
#pragma unroll
    for (int j = 0; j < 4; j++) {               // A: 128 rows x 8 segs of 16B
        int op = j * 256 + tid, row = op >> 3, seg = op & 7;
        CPA16(sA + row * (SPAD * 4) + seg * 16, abase + (size_t)row * apitch + seg * 4);
    }
    const float* wbase = g_w + k0;
#pragma unroll
    for (int j = 0; j < 4; j++) {               // B: 128 gathered gate rows x 8 segs
        int op = j * 256 + tid, rb = op >> 3, seg = op & 7;
        int n = ((rb >> 5) << 10) + nbase + (rb & 31);
        CPA16(sB + rb * (SPAD * 4) + seg * 16, wbase + (size_t)n * K_TOT + seg * 4);
    }
}

// ---------------- LSTM step ----------------
__global__ void __launch_bounds__(256, 2)
lstm_step_kernel(int t, const float* __restrict__ b_ih, const float* __restrict__ b_hh) {
    extern __shared__ char smem[];
    uint32_t sb = smem_u32(smem);
    int tid = threadIdx.x, wid = tid >> 5, lid = tid & 31;
    int wm = wid >> 2, wn = wid & 3;            // warp grid 2(m) x 4(n); warp tile 64x32
    int g = lid >> 2, tg = lid & 3;
    int m0 = blockIdx.x * MT, nbase = blockIdx.y * HT;

    const float* hin = (t & 1) ? g_h1 : g_h0;   // read-only this step
    float* hout      = (t & 1) ? g_h0 : g_h1;   // write-only this step

    if (tid < 128) {                            // bias for 128 gathered gate cols
        int n = ((tid >> 5) << 10) + nbase + (tid & 31);
        ((float*)smem)[tid] = b_ih[n] + b_hh[n];
    }

    float acc[4][4][4];                         // [mt][gate][quad]
#pragma unroll
    for (int mt = 0; mt < 4; mt++)
#pragma unroll
        for (int j = 0; j < 4; j++)
#pragma unroll
            for (int q = 0; q < 4; q++) acc[mt][j][q] = 0.0f;

    uint32_t stgA[NSTAGE], stgB[NSTAGE];
#pragma unroll
    for (int s = 0; s < NSTAGE; s++) {
        stgA[s] = sb + SM_STG0 + s * STG_BYTES;
        stgB[s] = stgA[s] + HALF_BYTES;
    }

    load_chunk(0, m0, nbase, stgA[0], stgB[0], t, tid, hin); CP_COMMIT();
    load_chunk(1, m0, nbase, stgA[1], stgB[1], t, tid, hin); CP_COMMIT();

    int st = 0;                                  // stage holding chunk kc
#pragma unroll 1
    for (int kc = 0; kc < NCHUNK; kc++) {
        if (kc + 2 < NCHUNK) {
            int ld = st + 2 - (st + 2 >= NSTAGE ? NSTAGE : 0);
            load_chunk(kc + 2, m0, nbase, stgA[ld], stgB[ld], t, tid, hin);
            CP_COMMIT();
            CP_WAIT_2();                        // chunk kc landed
        } else if (kc + 1 < NCHUNK) {
            CP_WAIT_1();
        } else {
            CP_WAIT_0();
        }
        __syncthreads();                        // chunk kc visible to all warps

        const float* As = (const float*)(smem + (stgA[st] - sb));
        const float* Bs = (const float*)(smem + (stgB[st] - sb));
#pragma unroll
        for (int ks = 0; ks < 4; ks++) {
            int k0 = ks * 8 + tg;
            uint32_t a[4][4], b[4][2];
#pragma unroll
            for (int mt = 0; mt < 4; mt++) {
                int r = wm * 64 + mt * 16 + g;
                a[mt][0] = __float_as_uint(As[r * SPAD + k0]);
                a[mt][1] = __float_as_uint(As[(r + 8) * SPAD + k0]);
                a[mt][2] = __float_as_uint(As[r * SPAD + k0 + 4]);
                a[mt][3] = __float_as_uint(As[(r + 8) * SPAD + k0 + 4]);
            }
#pragma unroll
            for (int j = 0; j < 4; j++) {       // j = gate
                int n = j * 32 + wn * 8 + g;
                b[j][0] = __float_as_uint(Bs[n * SPAD + k0]);
                b[j][1] = __float_as_uint(Bs[n * SPAD + k0 + 4]);
            }
#pragma unroll
            for (int mt = 0; mt < 4; mt++)
#pragma unroll
                for (int j = 0; j < 4; j++)
                    mma8(acc[mt][j], a[mt], b[j]);
        }
        __syncthreads();                        // all warps done reading stage st
        st = st + 1 == NSTAGE ? 0 : st + 1;
    }

    // epilogue: thread owns all 4 gates for its (row, h-col) pairs
    const float* bsm = (const float*)smem;
    int hc = wn * 8 + 2 * tg;                   // local h-col in [0,32)
    float bi0 = bsm[hc],       bi1 = bsm[hc + 1];
    float bf0 = bsm[32 + hc],  bf1 = bsm[32 + hc + 1];
    float bg0 = bsm[64 + hc],  bg1 = bsm[64 + hc + 1];
    float bo0 = bsm[96 + hc],  bo1 = bsm[96 + hc + 1];
#pragma unroll
    for (int mt = 0; mt < 4; mt++) {
        int rbase = m0 + wm * 64 + mt * 16 + g;
#pragma unroll
        for (int rr = 0; rr < 2; rr++) {
            int r = rbase + rr * 8;
            size_t off = (size_t)r * Hn + nbase + hc;
            float2 co = *(const float2*)(g_c + off);
            int q0 = rr * 2, q1 = rr * 2 + 1;
            float i0 = acc[mt][0][q0] + bi0, i1 = acc[mt][0][q1] + bi1;
            float f0 = acc[mt][1][q0] + bf0, f1 = acc[mt][1][q1] + bf1;
            float gg0 = acc[mt][2][q0] + bg0, gg1 = acc[mt][2][q1] + bg1;
            float o0 = acc[mt][3][q0] + bo0, o1 = acc[mt][3][q1] + bo1;
            float cn0 = sigf(f0) * co.x + sigf(i0) * tanhf_(gg0);
            float cn1 = sigf(f1) * co.y + sigf(i1) * tanhf_(gg1);
            float hn0 = tf32r(sigf(o0) * tanhf_(cn0));
            float hn1 = tf32r(sigf(o1) * tanhf_(cn1));
            *(float2*)(g_c + off) = make_float2(cn0, cn1);
            *(float2*)(hout + off) = make_float2(hn0, hn1);
        }
    }
}

// ---------------- final FC (reads g_h0: step 127 is odd -> writes buf0) ----------------
__global__ void fc_kernel(const float* __restrict__ w_fc, const float* __restrict__ b_fc,
                          float* __restrict__ out) {
    __shared__ float hs[Hn];
    int b = blockIdx.x;
    const float4* hsrc = (const float4*)(g_h0 + (size_t)b * Hn);
    for (int i = threadIdx.x; i < Hn / 4; i += 64) ((float4*)hs)[i] = hsrc[i];
    __syncthreads();
    int o = threadIdx.x;
    const float4* wr = (const float4*)(w_fc + (size_t)o * Hn);
    float acc = 0.0f;
#pragma unroll 8
    for (int k = 0; k < Hn / 4; k++) {
        float4 w4 = wr[k];
        float4 h4 = ((const float4*)hs)[k];
        acc += w4.x * h4.x + w4.y * h4.y + w4.z * h4.z + w4.w * h4.w;
    }
    out[b * On + o] = acc + b_fc[o];
}

extern "C" void kernel_launch(void* const* d_in, const int* in_sizes, int n_in,
                              void* d_out, int out_size) {
    (void)in_sizes; (void)n_in; (void)out_size;
    const float* x    = (const float*)d_in[0];
    const float* w_ih = (const float*)d_in[1];
    const float* w_hh = (const float*)d_in[2];
    const float* b_ih = (const float*)d_in[3];
    const float* b_hh = (const float*)d_in[4];
    const float* w_fc = (const float*)d_in[5];
    const float* b_fc = (const float*)d_in[6];
    float* out = (float*)d_out;

    cudaFuncSetAttribute(lstm_step_kernel, cudaFuncAttributeMaxDynamicSharedMemorySize, SMEM_BYTES);

    init_hc_kernel<<<(Bn * Hn) / 256, 256>>>();
    prep_w_kernel<<<(G4 * K_TOT + 255) / 256, 256>>>(w_ih, w_hh);
    prep_x_kernel<<<(Bn * Tn * In) / 256, 256>>>(x);

    dim3 grid(Bn / MT, Hn / HT);   // 8 x 32 = 256 CTAs -> 2 resident per SM
    for (int t = 0; t < Tn; t++)
        lstm_step_kernel<<<grid, 256, SMEM_BYTES>>>(t, b_ih, b_hh);

    fc_kernel<<<Bn, 64>>>(w_fc, b_fc, out);
}

// round 9
// speedup vs baseline: 1.9452x; 1.9452x over previous
#include <cuda_runtime.h>
#include <cuda_fp16.h>
#include <cstdint>

#define DEV_INLINE __device__ __forceinline__

constexpr int Bn = 1024, Tn = 128, In = 128, Hn = 1024, G4 = 4096, On = 64;
constexpr int K_TOT = In + Hn;          // 1152
constexpr int KC = 64;                  // K halves per chunk (128B rows)
constexpr int NCHUNK = K_TOT / KC;      // 18
constexpr int MT = 128;                 // M tile
constexpr int HT = 64;                  // h-cols per CTA (N tile = 4 gates x 64 = 256)
constexpr int WPAD = 36;                // row stride in 32-bit words (72 halves): banks 4g+tg
constexpr int NSTAGE = 3;

// ping-pong hidden state (fp16): step t reads buf[t&1], writes the other
__device__ __half g_h0[Bn * Hn];
__device__ __half g_h1[Bn * Hn];
__device__ float  g_c[Bn * Hn];
__device__ __half g_w[G4 * K_TOT];      // [w_ih | w_hh] fp16
__device__ __half g_x[Bn * Tn * In];    // fp16 x

constexpr int SM_STG0 = 1024;                          // bias floats in [0,1024)
constexpr int A_BYTES = MT * WPAD * 4;                 // 128 rows x 144B = 18432
constexpr int B_BYTES = 4 * HT * WPAD * 4;             // 256 rows x 144B = 36864
constexpr int STG_BYTES = A_BYTES + B_BYTES;           // 55296
constexpr int SMEM_BYTES = SM_STG0 + NSTAGE * STG_BYTES;  // 166912

#define CPA16(dst, src) asm volatile("cp.async.cg.shared.global [%0], [%1], 16;" :: "r"(dst), "l"(src))
#define CP_COMMIT()     asm volatile("cp.async.commit_group;" ::: "memory")
#define CP_WAIT_2()     asm volatile("cp.async.wait_group 2;" ::: "memory")
#define CP_WAIT_1()     asm volatile("cp.async.wait_group 1;" ::: "memory")
#define CP_WAIT_0()     asm volatile("cp.async.wait_group 0;" ::: "memory")

DEV_INLINE uint32_t smem_u32(const void* p) {
    uint32_t a;
    asm("{ .reg .u64 t; cvta.to.shared.u64 t, %1; cvt.u32.u64 %0, t; }" : "=r"(a) : "l"(p));
    return a;
}

DEV_INLINE void mma16(float* c, const uint32_t* a, const uint32_t* b) {
    asm volatile(
        "mma.sync.aligned.m16n8k16.row.col.f32.f16.f16.f32 "
        "{%0,%1,%2,%3}, {%4,%5,%6,%7}, {%8,%9}, {%0,%1,%2,%3};"
        : "+f"(c[0]), "+f"(c[1]), "+f"(c[2]), "+f"(c[3])
        : "r"(a[0]), "r"(a[1]), "r"(a[2]), "r"(a[3]), "r"(b[0]), "r"(b[1]));
}

DEV_INLINE float sigf(float x) {
    float e, r;
    asm("ex2.approx.f32 %0, %1;" : "=f"(e) : "f"(-1.4426950408889634f * x));
    asm("rcp.approx.f32 %0, %1;" : "=f"(r) : "f"(1.0f + e));
    return r;
}
DEV_INLINE float tanhf_(float x) { return 2.0f * sigf(2.0f * x) - 1.0f; }

// ---------------- prep ----------------
__global__ void init_hc_kernel() {
    int i = blockIdx.x * blockDim.x + threadIdx.x;
    if (i < Bn * Hn) {
        g_h0[i] = __float2half(0.0f);
        g_h1[i] = __float2half(0.0f);
        g_c[i] = 0.0f;
    }
}
__global__ void prep_w_kernel(const float* __restrict__ w_ih, const float* __restrict__ w_hh) {
    int i = blockIdx.x * blockDim.x + threadIdx.x;
    if (i >= G4 * K_TOT) return;
    int n = i / K_TOT, k = i - n * K_TOT;
    g_w[i] = __float2half_rn(k < In ? w_ih[n * In + k] : w_hh[n * Hn + (k - In)]);
}
__global__ void prep_x_kernel(const float* __restrict__ x) {
    int i = blockIdx.x * blockDim.x + threadIdx.x;
    if (i < Bn * Tn * In) g_x[i] = __float2half_rn(x[i]);
}

// ---------------- chunk loader: A 128x64h, B 256x64h, rows padded to 144B ----------------
DEV_INLINE void load_chunk(int kc, int m0, int nbase, uint32_t sA, uint32_t sB,
                           int t, int tid, const __half* __restrict__ hin) {
    int k0 = kc * KC;                           // in halves
    const __half* abase;
    int apitch;
    if (k0 < In) { abase = g_x + (size_t)m0 * (Tn * In) + t * In + k0; apitch = Tn * In; }
    else         { abase = hin + (size_t)m0 * Hn + (k0 - In);          apitch = Hn; }
#pragma unroll
    for (int j = 0; j < 4; j++) {               // A: 128 rows x 8 segs of 16B
        int op = j * 256 + tid, row = op >> 3, seg = op & 7;
        CPA16(sA + row * 144 + seg * 16, abase + (size_t)row * apitch + seg * 8);
    }
    const __half* wbase = g_w + k0;
#pragma unroll
    for (int j = 0; j < 8; j++) {               // B: 256 gathered gate rows x 8 segs
        int op = j * 256 + tid, rb = op >> 3, seg = op & 7;
        int n = ((rb >> 6) << 10) + nbase + (rb & 63);
        CPA16(sB + rb * 144 + seg * 16, wbase + (size_t)n * K_TOT + seg * 8);
    }
}

// ---------------- LSTM step ----------------
__global__ void __launch_bounds__(256, 1)
lstm_step_kernel(int t, const float* __restrict__ b_ih, const float* __restrict__ b_hh) {
    extern __shared__ char smem[];
    uint32_t sb = smem_u32(smem);
    int tid = threadIdx.x, wid = tid >> 5, lid = tid & 31;
    int wm = wid >> 2, wn = wid & 3;            // warp grid 2(m) x 4(n); warp tile 64x64
    int g = lid >> 2, tg = lid & 3;
    int m0 = blockIdx.x * MT, nbase = blockIdx.y * HT;

    const __half* hin = (t & 1) ? g_h1 : g_h0;
    __half* hout      = (t & 1) ? g_h0 : g_h1;

    {   // bias for 256 gathered gate cols
        int n = ((tid >> 6) << 10) + nbase + (tid & 63);
        ((float*)smem)[tid] = b_ih[n] + b_hh[n];
    }

    float acc[4][8][4];                         // [mt][2*gate+sub][quad]
#pragma unroll
    for (int mt = 0; mt < 4; mt++)
#pragma unroll
        for (int j = 0; j < 8; j++)
#pragma unroll
            for (int q = 0; q < 4; q++) acc[mt][j][q] = 0.0f;

    uint32_t stgA[NSTAGE], stgB[NSTAGE];
#pragma unroll
    for (int s = 0; s < NSTAGE; s++) {
        stgA[s] = sb + SM_STG0 + s * STG_BYTES;
        stgB[s] = stgA[s] + A_BYTES;
    }

    load_chunk(0, m0, nbase, stgA[0], stgB[0], t, tid, hin); CP_COMMIT();
    load_chunk(1, m0, nbase, stgA[1], stgB[1], t, tid, hin); CP_COMMIT();

    int st = 0;
#pragma unroll 1
    for (int kc = 0; kc < NCHUNK; kc++) {
        if (kc + 2 < NCHUNK) {
            int ld = st + 2 - (st + 2 >= NSTAGE ? NSTAGE : 0);
            load_chunk(kc + 2, m0, nbase, stgA[ld], stgB[ld], t, tid, hin);
            CP_COMMIT();
            CP_WAIT_2();
        } else if (kc + 1 < NCHUNK) {
            CP_WAIT_1();
        } else {
            CP_WAIT_0();
        }
        __syncthreads();                        // chunk kc visible

        const uint32_t* As = (const uint32_t*)(smem + (stgA[st] - sb));
        const uint32_t* Bs = (const uint32_t*)(smem + (stgB[st] - sb));
#pragma unroll
        for (int ks = 0; ks < 4; ks++) {        // 4 k16-steps per 64-half chunk
            int kw = ks * 8 + tg;               // word offset within padded row
            uint32_t a[4][4], b[8][2];
#pragma unroll
            for (int mt = 0; mt < 4; mt++) {
                int r = wm * 64 + mt * 16 + g;
                a[mt][0] = As[r * WPAD + kw];
                a[mt][1] = As[(r + 8) * WPAD + kw];
                a[mt][2] = As[r * WPAD + kw + 4];
                a[mt][3] = As[(r + 8) * WPAD + kw + 4];
            }
#pragma unroll
            for (int j = 0; j < 8; j++) {       // n-tiles strided across gates
                int n = (j >> 1) * 64 + wn * 16 + (j & 1) * 8 + g;
                b[j][0] = Bs[n * WPAD + kw];
                b[j][1] = Bs[n * WPAD + kw + 4];
            }
#pragma unroll
            for (int mt = 0; mt < 4; mt++)
#pragma unroll
                for (int j = 0; j < 8; j++)
                    mma16(acc[mt][j], a[mt], b[j]);
        }
        __syncthreads();                        // done reading stage st
        st = st + 1 == NSTAGE ? 0 : st + 1;
    }

    // epilogue: thread owns all 4 gates for its (row, h-col) pairs
    const float* bsm = (const float*)smem;
#pragma unroll
    for (int mt = 0; mt < 4; mt++) {
        int rbase = m0 + wm * 64 + mt * 16 + g;
#pragma unroll
        for (int sub = 0; sub < 2; sub++) {
            int hc = wn * 16 + sub * 8 + 2 * tg;     // local h-col in [0,64)
            float bi0 = bsm[hc],        bi1 = bsm[hc + 1];
            float bf0 = bsm[64 + hc],   bf1 = bsm[64 + hc + 1];
            float bg0 = bsm[128 + hc],  bg1 = bsm[128 + hc + 1];
            float bo0 = bsm[192 + hc],  bo1 = bsm[192 + hc + 1];
#pragma unroll
            for (int rr = 0; rr < 2; rr++) {
                int r = rbase + rr * 8;
                size_t off = (size_t)r * Hn + nbase + hc;
                float2 co = *(const float2*)(g_c + off);
                int q0 = rr * 2, q1 = rr * 2 + 1;
                float i0 = acc[mt][0 + sub][q0] + bi0, i1 = acc[mt][0 + sub][q1] + bi1;
                float f0 = acc[mt][2 + sub][q0] + bf0, f1 = acc[mt][2 + sub][q1] + bf1;
                float gg0 = acc[mt][4 + sub][q0] + bg0, gg1 = acc[mt][4 + sub][q1] + bg1;
                float o0 = acc[mt][6 + sub][q0] + bo0, o1 = acc[mt][6 + sub][q1] + bo1;
                float cn0 = sigf(f0) * co.x + sigf(i0) * tanhf_(gg0);
                float cn1 = sigf(f1) * co.y + sigf(i1) * tanhf_(gg1);
                *(float2*)(g_c + off) = make_float2(cn0, cn1);
                __half2 hv = __floats2half2_rn(sigf(o0) * tanhf_(cn0),
                                               sigf(o1) * tanhf_(cn1));
                *(__half2*)(hout + off) = hv;
            }
        }
    }
}

// ---------------- final FC (t=127 odd -> final h in g_h0) ----------------
__global__ void fc_kernel(const float* __restrict__ w_fc, const float* __restrict__ b_fc,
                          float* __restrict__ out) {
    __shared__ float hs[Hn];
    int b = blockIdx.x;
    const __half2* hsrc = (const __half2*)(g_h0 + (size_t)b * Hn);
    for (int i = threadIdx.x; i < Hn / 2; i += 64) {
        float2 v = __half22float2(hsrc[i]);
        hs[2 * i] = v.x; hs[2 * i + 1] = v.y;
    }
    __syncthreads();
    int o = threadIdx.x;
    const float4* wr = (const float4*)(w_fc + (size_t)o * Hn);
    float acc = 0.0f;
#pragma unroll 8
    for (int k = 0; k < Hn / 4; k++) {
        float4 w4 = wr[k];
        float4 h4 = ((const float4*)hs)[k];
        acc += w4.x * h4.x + w4.y * h4.y + w4.z * h4.z + w4.w * h4.w;
    }
    out[b * On + o] = acc + b_fc[o];
}

extern "C" void kernel_launch(void* const* d_in, const int* in_sizes, int n_in,
                              void* d_out, int out_size) {
    (void)in_sizes; (void)n_in; (void)out_size;
    const float* x    = (const float*)d_in[0];
    const float* w_ih = (const float*)d_in[1];
    const float* w_hh = (const float*)d_in[2];
    const float* b_ih = (const float*)d_in[3];
    const float* b_hh = (const float*)d_in[4];
    const float* w_fc = (const float*)d_in[5];
    const float* b_fc = (const float*)d_in[6];
    float* out = (float*)d_out;

    cudaFuncSetAttribute(lstm_step_kernel, cudaFuncAttributeMaxDynamicSharedMemorySize, SMEM_BYTES);

    init_hc_kernel<<<(Bn * Hn) / 256, 256>>>();
    prep_w_kernel<<<(G4 * K_TOT + 255) / 256, 256>>>(w_ih, w_hh);
    prep_x_kernel<<<(Bn * Tn * In) / 256, 256>>>(x);

    dim3 grid(Bn / MT, Hn / HT);   // 8 x 16 = 128 CTAs
    for (int t = 0; t < Tn; t++)
        lstm_step_kernel<<<grid, 256, SMEM_BYTES>>>(t, b_ih, b_hh);

    fc_kernel<<<Bn, 64>>>(w_fc, b_fc, out);
}

// round 10
// speedup vs baseline: 1.9592x; 1.0072x over previous
#include <cuda_runtime.h>
#include <cuda_fp16.h>
#include <cstdint>

#define DEV_INLINE __device__ __forceinline__

constexpr int Bn = 1024, Tn = 128, In = 128, Hn = 1024, G4 = 4096, On = 64;
constexpr int K_TOT = In + Hn;          // 1152
constexpr int KC = 128;                 // K halves per chunk (256B rows)
constexpr int NCHUNK = K_TOT / KC;      // 9  (chunk 0 = x, chunks 1..8 = h)
constexpr int MT = 128;                 // M tile
constexpr int HT = 64;                  // h-cols per CTA (N = 4 gates x 64 = 256)
constexpr int WPAD = 68;                // words per row (64 + 4 pad) -> conflict-free LDS
constexpr int NGRID = (Bn / MT) * (Hn / HT);   // 128 CTAs

// ping-pong hidden state (fp16): step t reads buf[t&1], writes the other
__device__ __half g_h0[Bn * Hn];
__device__ __half g_h1[Bn * Hn];
__device__ float  g_c[Bn * Hn];
__device__ __half g_w[G4 * K_TOT];      // [w_ih | w_hh] fp16
__device__ __half g_x[Bn * Tn * In];    // fp16 x
__device__ unsigned g_bar_ctr = 0;      // grid barrier state (returns to 0 each launch)
__device__ unsigned g_bar_sense = 0;

constexpr int SM_STG0 = 1024;                       // bias floats in [0,1024)
constexpr int A_BYTES = MT * WPAD * 4;              // 34816
constexpr int B_BYTES = 4 * HT * WPAD * 4;          // 69632
constexpr int STG_BYTES = A_BYTES + B_BYTES;        // 104448
constexpr int SMEM_BYTES = SM_STG0 + 2 * STG_BYTES; // 209920

#define CPA16(dst, src) asm volatile("cp.async.cg.shared.global [%0], [%1], 16;" :: "r"(dst), "l"(src))
#define CP_COMMIT()     asm volatile("cp.async.commit_group;" ::: "memory")
#define CP_WAIT_0()     asm volatile("cp.async.wait_group 0;" ::: "memory")

DEV_INLINE uint32_t smem_u32(const void* p) {
    uint32_t a;
    asm("{ .reg .u64 t; cvta.to.shared.u64 t, %1; cvt.u32.u64 %0, t; }" : "=r"(a) : "l"(p));
    return a;
}

DEV_INLINE void mma16(float* c, const uint32_t* a, const uint32_t* b) {
    asm volatile(
        "mma.sync.aligned.m16n8k16.row.col.f32.f16.f16.f32 "
        "{%0,%1,%2,%3}, {%4,%5,%6,%7}, {%8,%9}, {%0,%1,%2,%3};"
        : "+f"(c[0]), "+f"(c[1]), "+f"(c[2]), "+f"(c[3])
        : "r"(a[0]), "r"(a[1]), "r"(a[2]), "r"(a[3]), "r"(b[0]), "r"(b[1]));
}

DEV_INLINE float sigf(float x) {
    float e, r;
    asm("ex2.approx.f32 %0, %1;" : "=f"(e) : "f"(-1.4426950408889634f * x));
    asm("rcp.approx.f32 %0, %1;" : "=f"(r) : "f"(1.0f + e));
    return r;
}
DEV_INLINE float tanhf_(float x) { return 2.0f * sigf(2.0f * x) - 1.0f; }

// ---------------- prep ----------------
__global__ void init_hc_kernel() {
    int i = blockIdx.x * blockDim.x + threadIdx.x;
    if (i < Bn * Hn) {
        g_h0[i] = __float2half(0.0f);
        g_h1[i] = __float2half(0.0f);
        g_c[i] = 0.0f;
    }
    if (i == 0) { g_bar_ctr = 0; g_bar_sense = 0; }
}
__global__ void prep_w_kernel(const float* __restrict__ w_ih, const float* __restrict__ w_hh) {
    int i = blockIdx.x * blockDim.x + threadIdx.x;
    if (i >= G4 * K_TOT) return;
    int n = i / K_TOT, k = i - n * K_TOT;
    g_w[i] = __float2half_rn(k < In ? w_ih[n * In + k] : w_hh[n * Hn + (k - In)]);
}
__global__ void prep_x_kernel(const float* __restrict__ x) {
    int i = blockIdx.x * blockDim.x + threadIdx.x;
    if (i < Bn * Tn * In) g_x[i] = __float2half_rn(x[i]);
}

// ---------------- chunk loader: A 128x128h, B 256x128h, rows padded to 272B ----------------
DEV_INLINE void load_chunk(int kc, int m0, int nbase, uint32_t sA, uint32_t sB,
                           int t, int tid, const __half* __restrict__ hin) {
    int k0 = kc * KC;                           // in halves
    const __half* abase;
    int apitch;
    if (kc == 0) { abase = g_x + (size_t)m0 * (Tn * In) + t * In; apitch = Tn * In; }
    else         { abase = hin + (size_t)m0 * Hn + (k0 - In);     apitch = Hn; }
#pragma unroll
    for (int j = 0; j < 8; j++) {               // A: 128 rows x 16 segs of 16B
        int op = j * 256 + tid, row = op >> 4, seg = op & 15;
        CPA16(sA + row * (WPAD * 4) + seg * 16, abase + (size_t)row * apitch + seg * 8);
    }
    const __half* wbase = g_w + k0;
#pragma unroll
    for (int j = 0; j < 16; j++) {              // B: 256 gathered gate rows x 16 segs
        int op = j * 256 + tid, rb = op >> 4, seg = op & 15;
        int n = ((rb >> 6) << 10) + nbase + (rb & 63);
        CPA16(sB + rb * (WPAD * 4) + seg * 16, wbase + (size_t)n * K_TOT + seg * 8);
    }
}

// ---------------- persistent LSTM kernel ----------------
__global__ void __launch_bounds__(256, 1)
lstm_persistent_kernel(const float* __restrict__ b_ih, const float* __restrict__ b_hh) {
    extern __shared__ char smem[];
    uint32_t sb = smem_u32(smem);
    int tid = threadIdx.x, wid = tid >> 5, lid = tid & 31;
    int wm = wid >> 2, wn = wid & 3;            // warp grid 2(m) x 4(n); warp tile 64x64
    int g = lid >> 2, tg = lid & 3;
    int m0 = blockIdx.x * MT, nbase = blockIdx.y * HT;

    {   // bias for 256 gathered gate cols (loaded ONCE for all 128 steps)
        int n = ((tid >> 6) << 10) + nbase + (tid & 63);
        ((float*)smem)[tid] = b_ih[n] + b_hh[n];
    }
    __syncthreads();

    float binit[8][2];                          // bias per (j, col-pair) for acc init
    const float* bsm = (const float*)smem;
#pragma unroll
    for (int j = 0; j < 8; j++) {
        int col = (j >> 1) * 64 + wn * 16 + (j & 1) * 8 + 2 * tg;
        binit[j][0] = bsm[col];
        binit[j][1] = bsm[col + 1];
    }

    uint32_t stgA[2], stgB[2];
#pragma unroll
    for (int s = 0; s < 2; s++) {
        stgA[s] = sb + SM_STG0 + s * STG_BYTES;
        stgB[s] = stgA[s] + A_BYTES;
    }

    // preload chunk 0 of step 0 (x-only; hin unused)
    load_chunk(0, m0, nbase, stgA[0], stgB[0], 0, tid, g_h0);
    CP_COMMIT();

    unsigned sense = 0;

#pragma unroll 1
    for (int t = 0; t < Tn; t++) {
        const __half* hin = (t & 1) ? g_h1 : g_h0;
        __half* hout      = (t & 1) ? g_h0 : g_h1;

        float acc[4][8][4];                     // init with bias
#pragma unroll
        for (int mt = 0; mt < 4; mt++)
#pragma unroll
            for (int j = 0; j < 8; j++) {
                acc[mt][j][0] = binit[j][0]; acc[mt][j][1] = binit[j][1];
                acc[mt][j][2] = binit[j][0]; acc[mt][j][3] = binit[j][1];
            }

#pragma unroll 1
        for (int kc = 0; kc < NCHUNK; kc++) {
            CP_WAIT_0();                        // chunk kc (sole outstanding group) landed
            __syncthreads();                    // visible to all warps; prev stage consumed
            int sc = (t + kc) & 1;              // stage of chunk kc (9 chunks/step -> parity flips)
            int nidx = kc + 1;
            if (nidx < NCHUNK)
                load_chunk(nidx, m0, nbase, stgA[sc ^ 1], stgB[sc ^ 1], t, tid, hin);
            else if (t + 1 < Tn)                // next step's chunk 0 = pure x, no h dep
                load_chunk(0, m0, nbase, stgA[sc ^ 1], stgB[sc ^ 1], t + 1, tid, hin);
            CP_COMMIT();                        // always commit (uniform group accounting)

            const uint32_t* As = (const uint32_t*)(smem + (stgA[sc] - sb));
            const uint32_t* Bs = (const uint32_t*)(smem + (stgB[sc] - sb));
#pragma unroll
            for (int ks = 0; ks < 8; ks++) {    // 8 k16-steps per 128-half chunk
                int kw = ks * 8 + tg;
                uint32_t a[4][4], b[8][2];
#pragma unroll
                for (int mt = 0; mt < 4; mt++) {
                    int r = wm * 64 + mt * 16 + g;
                    a[mt][0] = As[r * WPAD + kw];
                    a[mt][1] = As[(r + 8) * WPAD + kw];
                    a[mt][2] = As[r * WPAD + kw + 4];
                    a[mt][3] = As[(r + 8) * WPAD + kw + 4];
                }
#pragma unroll
                for (int j = 0; j < 8; j++) {   // n-tiles strided across gates
                    int n = (j >> 1) * 64 + wn * 16 + (j & 1) * 8 + g;
                    b[j][0] = Bs[n * WPAD + kw];
                    b[j][1] = Bs[n * WPAD + kw + 4];
                }
#pragma unroll
                for (int mt = 0; mt < 4; mt++)
#pragma unroll
                    for (int j = 0; j < 8; j++)
                        mma16(acc[mt][j], a[mt], b[j]);
            }
        }

        // epilogue: bias already in acc
#pragma unroll
        for (int mt = 0; mt < 4; mt++) {
            int rbase = m0 + wm * 64 + mt * 16 + g;
#pragma unroll
            for (int sub = 0; sub < 2; sub++) {
                int hc = wn * 16 + sub * 8 + 2 * tg;
#pragma unroll
                for (int rr = 0; rr < 2; rr++) {
                    int r = rbase + rr * 8;
                    size_t off = (size_t)r * Hn + nbase + hc;
                    float2 co = *(const float2*)(g_c + off);
                    int q0 = rr * 2, q1 = rr * 2 + 1;
                    float i0 = acc[mt][0 + sub][q0], i1 = acc[mt][0 + sub][q1];
                    float f0 = acc[mt][2 + sub][q0], f1 = acc[mt][2 + sub][q1];
                    float gg0 = acc[mt][4 + sub][q0], gg1 = acc[mt][4 + sub][q1];
                    float o0 = acc[mt][6 + sub][q0], o1 = acc[mt][6 + sub][q1];
                    float cn0 = sigf(f0) * co.x + sigf(i0) * tanhf_(gg0);
                    float cn1 = sigf(f1) * co.y + sigf(i1) * tanhf_(gg1);
                    *(float2*)(g_c + off) = make_float2(cn0, cn1);
                    __half2 hv = __floats2half2_rn(sigf(o0) * tanhf_(cn0),
                                                   sigf(o1) * tanhf_(cn1));
                    *(__half2*)(hout + off) = hv;
                }
            }
        }

        // grid barrier (sense-reversing; 128 barriers/launch -> state returns to 0)
        __threadfence();                        // publish this CTA's h/c stores
        __syncthreads();
        if (tid == 0) {
            sense ^= 1u;
            unsigned pos = atomicAdd(&g_bar_ctr, 1u);
            if (pos == NGRID - 1) {
                atomicExch(&g_bar_ctr, 0u);
                __threadfence();
                atomicExch(&g_bar_sense, sense);
            } else {
                volatile unsigned* vs = &g_bar_sense;
                while (*vs != sense) __nanosleep(32);
                __threadfence();
            }
        }
        __syncthreads();
    }
}

// ---------------- final FC (t=127 odd -> final h in g_h0) ----------------
__global__ void fc_kernel(const float* __restrict__ w_fc, const float* __restrict__ b_fc,
                          float* __restrict__ out) {
    __shared__ float hs[Hn];
    int b = blockIdx.x;
    const __half2* hsrc = (const __half2*)(g_h0 + (size_t)b * Hn);
    for (int i = threadIdx.x; i < Hn / 2; i += 64) {
        float2 v = __half22float2(hsrc[i]);
        hs[2 * i] = v.x; hs[2 * i + 1] = v.y;
    }
    __syncthreads();
    int o = threadIdx.x;
    const float4* wr = (const float4*)(w_fc + (size_t)o * Hn);
    float acc = 0.0f;
#pragma unroll 8
    for (int k = 0; k < Hn / 4; k++) {
        float4 w4 = wr[k];
        float4 h4 = ((const float4*)hs)[k];
        acc += w4.x * h4.x + w4.y * h4.y + w4.z * h4.z + w4.w * h4.w;
    }
    out[b * On + o] = acc + b_fc[o];
}

extern "C" void kernel_launch(void* const* d_in, const int* in_sizes, int n_in,
                              void* d_out, int out_size) {
    (void)in_sizes; (void)n_in; (void)out_size;
    const float* x    = (const float*)d_in[0];
    const float* w_ih = (const float*)d_in[1];
    const float* w_hh = (const float*)d_in[2];
    const float* b_ih = (const float*)d_in[3];
    const float* b_hh = (const float*)d_in[4];
    const float* w_fc = (const float*)d_in[5];
    const float* b_fc = (const float*)d_in[6];
    float* out = (float*)d_out;

    cudaFuncSetAttribute(lstm_persistent_kernel,
                         cudaFuncAttributeMaxDynamicSharedMemorySize, SMEM_BYTES);

    init_hc_kernel<<<(Bn * Hn) / 256, 256>>>();
    prep_w_kernel<<<(G4 * K_TOT + 255) / 256, 256>>>(w_ih, w_hh);
    prep_x_kernel<<<(Bn * Tn * In) / 256, 256>>>(x);

    dim3 grid(Bn / MT, Hn / HT);   // 8 x 16 = 128 CTAs, all co-resident (1/SM)
    lstm_persistent_kernel<<<grid, 256, SMEM_BYTES>>>(b_ih, b_hh);

    fc_kernel<<<Bn, 64>>>(w_fc, b_fc, out);
}

// round 11
// speedup vs baseline: 1.9602x; 1.0005x over previous
#include <cuda_runtime.h>
#include <cuda_fp16.h>
#include <cstdint>

#define DEV_INLINE __device__ __forceinline__

constexpr int Bn = 1024, Tn = 128, In = 128, Hn = 1024, G4 = 4096, On = 64;
constexpr int K_TOT = In + Hn;          // 1152
constexpr int KC = 128;                 // K halves per chunk
constexpr int NCHUNK = K_TOT / KC;      // 9  (chunk 0 = x, chunks 1..8 = h)
constexpr int MT = 128;                 // M tile
constexpr int HT = 64;                  // h-cols per CTA (N = 4 gates x 64 = 256)
constexpr int WPAD = 68;                // words per row (272B) -> conflict-free LDS/ldmatrix
constexpr int ROWB = WPAD * 4;          // 272
constexpr int NGRID = (Bn / MT) * (Hn / HT);   // 128 CTAs

__device__ __half g_h0[Bn * Hn];
__device__ __half g_h1[Bn * Hn];
__device__ float  g_c[Bn * Hn];
__device__ __half g_w[G4 * K_TOT];
__device__ __half g_x[Bn * Tn * In];
__device__ unsigned g_bar_ctr = 0;
__device__ unsigned g_bar_sense = 0;

constexpr int SM_STG0 = 1024;                       // bias floats in [0,1024)
constexpr int A_BYTES = MT * ROWB;                  // 34816
constexpr int B_BYTES = 4 * HT * ROWB;              // 69632
constexpr int STG_BYTES = A_BYTES + B_BYTES;        // 104448
constexpr int SMEM_BYTES = SM_STG0 + 2 * STG_BYTES; // 209920

#define CPA16(dst, src) asm volatile("cp.async.cg.shared.global [%0], [%1], 16;" :: "r"(dst), "l"(src))
#define CP_COMMIT()     asm volatile("cp.async.commit_group;" ::: "memory")
#define CP_WAIT_0()     asm volatile("cp.async.wait_group 0;" ::: "memory")

DEV_INLINE uint32_t smem_u32(const void* p) {
    uint32_t a;
    asm("{ .reg .u64 t; cvta.to.shared.u64 t, %1; cvt.u32.u64 %0, t; }" : "=r"(a) : "l"(p));
    return a;
}

DEV_INLINE void ldsm4(uint32_t& r0, uint32_t& r1, uint32_t& r2, uint32_t& r3, uint32_t addr) {
    asm volatile("ldmatrix.sync.aligned.m8n8.x4.shared.b16 {%0,%1,%2,%3}, [%4];"
                 : "=r"(r0), "=r"(r1), "=r"(r2), "=r"(r3) : "r"(addr));
}

DEV_INLINE void mma16(float* c, const uint32_t* a, const uint32_t* b) {
    asm volatile(
        "mma.sync.aligned.m16n8k16.row.col.f32.f16.f16.f32 "
        "{%0,%1,%2,%3}, {%4,%5,%6,%7}, {%8,%9}, {%0,%1,%2,%3};"
        : "+f"(c[0]), "+f"(c[1]), "+f"(c[2]), "+f"(c[3])
        : "r"(a[0]), "r"(a[1]), "r"(a[2]), "r"(a[3]), "r"(b[0]), "r"(b[1]));
}

DEV_INLINE float sigf(float x) {
    float e, r;
    asm("ex2.approx.f32 %0, %1;" : "=f"(e) : "f"(-1.4426950408889634f * x));
    asm("rcp.approx.f32 %0, %1;" : "=f"(r) : "f"(1.0f + e));
    return r;
}
DEV_INLINE float tanhf_(float x) { return 2.0f * sigf(2.0f * x) - 1.0f; }

// ---------------- prep ----------------
__global__ void init_hc_kernel() {
    int i = blockIdx.x * blockDim.x + threadIdx.x;
    if (i < Bn * Hn) {
        g_h0[i] = __float2half(0.0f);
        g_h1[i] = __float2half(0.0f);
        g_c[i] = 0.0f;
    }
    if (i == 0) { g_bar_ctr = 0; g_bar_sense = 0; }
}
__global__ void prep_w_kernel(const float* __restrict__ w_ih, const float* __restrict__ w_hh) {
    int i = blockIdx.x * blockDim.x + threadIdx.x;
    if (i >= G4 * K_TOT) return;
    int n = i / K_TOT, k = i - n * K_TOT;
    g_w[i] = __float2half_rn(k < In ? w_ih[n * In + k] : w_hh[n * Hn + (k - In)]);
}
__global__ void prep_x_kernel(const float* __restrict__ x) {
    int i = blockIdx.x * blockDim.x + threadIdx.x;
    if (i < Bn * Tn * In) g_x[i] = __float2half_rn(x[i]);
}

// ---------------- chunk loader ----------------
DEV_INLINE void load_chunk(int kc, int m0, int nbase, uint32_t sA, uint32_t sB,
                           int t, int tid, const __half* __restrict__ hin) {
    int k0 = kc * KC;
    const __half* abase;
    int apitch;
    if (kc == 0) { abase = g_x + (size_t)m0 * (Tn * In) + t * In; apitch = Tn * In; }
    else         { abase = hin + (size_t)m0 * Hn + (k0 - In);     apitch = Hn; }
#pragma unroll
    for (int j = 0; j < 8; j++) {               // A: 128 rows x 16 segs of 16B
        int op = j * 256 + tid, row = op >> 4, seg = op & 15;
        CPA16(sA + row * ROWB + seg * 16, abase + (size_t)row * apitch + seg * 8);
    }
    const __half* wbase = g_w + k0;
#pragma unroll
    for (int j = 0; j < 16; j++) {              // B: 256 gathered gate rows x 16 segs
        int op = j * 256 + tid, rb = op >> 4, seg = op & 15;
        int n = ((rb >> 6) << 10) + nbase + (rb & 63);
        CPA16(sB + rb * ROWB + seg * 16, wbase + (size_t)n * K_TOT + seg * 8);
    }
}

// ---------------- persistent LSTM kernel ----------------
__global__ void __launch_bounds__(256, 1)
lstm_persistent_kernel(const float* __restrict__ b_ih, const float* __restrict__ b_hh) {
    extern __shared__ char smem[];
    uint32_t sb = smem_u32(smem);
    int tid = threadIdx.x, wid = tid >> 5, lid = tid & 31;
    int wm = wid >> 2, wn = wid & 3;            // warp grid 2(m) x 4(n); warp tile 64x64
    int g = lid >> 2, tg = lid & 3;
    int m0 = blockIdx.x * MT, nbase = blockIdx.y * HT;

    {   // bias for 256 gathered gate cols (once for all steps)
        int n = ((tid >> 6) << 10) + nbase + (tid & 63);
        ((float*)smem)[tid] = b_ih[n] + b_hh[n];
    }
    __syncthreads();

    // ldmatrix per-lane offsets
    int mrow = ((lid >> 3) & 1) * 8 + (lid & 7);
    uint32_t aoff = (uint32_t)(mrow * ROWB + (lid >> 4) * 16);                  // A lanes
    uint32_t boff = (uint32_t)(((lid >> 4) * 8 + (lid & 7)) * ROWB + ((lid >> 3) & 1) * 16);

    uint32_t stgA[2], stgB[2];
#pragma unroll
    for (int s = 0; s < 2; s++) {
        stgA[s] = sb + SM_STG0 + s * STG_BYTES;
        stgB[s] = stgA[s] + A_BYTES;
    }

    load_chunk(0, m0, nbase, stgA[0], stgB[0], 0, tid, g_h0);
    CP_COMMIT();

    unsigned sense = 0;

#pragma unroll 1
    for (int t = 0; t < Tn; t++) {
        const __half* hin = (t & 1) ? g_h1 : g_h0;
        __half* hout      = (t & 1) ? g_h0 : g_h1;

        float acc[4][8][4];
#pragma unroll
        for (int mt = 0; mt < 4; mt++)
#pragma unroll
            for (int j = 0; j < 8; j++)
#pragma unroll
                for (int q = 0; q < 4; q++) acc[mt][j][q] = 0.0f;

#pragma unroll 1
        for (int kc = 0; kc < NCHUNK; kc++) {
            CP_WAIT_0();
            __syncthreads();
            int sc = (t + kc) & 1;
            int nidx = kc + 1;
            if (nidx < NCHUNK)
                load_chunk(nidx, m0, nbase, stgA[sc ^ 1], stgB[sc ^ 1], t, tid, hin);
            else if (t + 1 < Tn)
                load_chunk(0, m0, nbase, stgA[sc ^ 1], stgB[sc ^ 1], t + 1, tid, hin);
            CP_COMMIT();

            uint32_t aA = stgA[sc] + (uint32_t)(wm * 64 * ROWB) + aoff;
            uint32_t bA = stgB[sc] + (uint32_t)(wn * 16 * ROWB) + boff;

            uint32_t aq[2][4][4], bq[2][8][2];
            // prime ks=0 fragments
#pragma unroll
            for (int mt = 0; mt < 4; mt++)
                ldsm4(aq[0][mt][0], aq[0][mt][1], aq[0][mt][2], aq[0][mt][3],
                      aA + mt * (16 * ROWB));
#pragma unroll
            for (int s = 0; s < 4; s++)
                ldsm4(bq[0][2 * s][0], bq[0][2 * s][1], bq[0][2 * s + 1][0], bq[0][2 * s + 1][1],
                      bA + s * (64 * ROWB));

#pragma unroll
            for (int ks = 0; ks < 8; ks++) {
                int cb = ks & 1, nb = cb ^ 1;
                if (ks < 7) {                   // prefetch ks+1 fragments
                    uint32_t ko = (uint32_t)((ks + 1) * 32);
#pragma unroll
                    for (int mt = 0; mt < 4; mt++)
                        ldsm4(aq[nb][mt][0], aq[nb][mt][1], aq[nb][mt][2], aq[nb][mt][3],
                              aA + mt * (16 * ROWB) + ko);
#pragma unroll
                    for (int s = 0; s < 4; s++)
                        ldsm4(bq[nb][2 * s][0], bq[nb][2 * s][1],
                              bq[nb][2 * s + 1][0], bq[nb][2 * s + 1][1],
                              bA + s * (64 * ROWB) + ko);
                }
#pragma unroll
                for (int mt = 0; mt < 4; mt++)
#pragma unroll
                    for (int j = 0; j < 8; j++)
                        mma16(acc[mt][j], aq[cb][mt], bq[cb][j]);
            }
        }

        // epilogue: add bias, LSTM pointwise, write h/c
        const float* bsm = (const float*)smem;
#pragma unroll
        for (int mt = 0; mt < 4; mt++) {
            int rbase = m0 + wm * 64 + mt * 16 + g;
#pragma unroll
            for (int sub = 0; sub < 2; sub++) {
                int hc = wn * 16 + sub * 8 + 2 * tg;
                float bi0 = bsm[hc],        bi1 = bsm[hc + 1];
                float bf0 = bsm[64 + hc],   bf1 = bsm[64 + hc + 1];
                float bg0 = bsm[128 + hc],  bg1 = bsm[128 + hc + 1];
                float bo0 = bsm[192 + hc],  bo1 = bsm[192 + hc + 1];
#pragma unroll
                for (int rr = 0; rr < 2; rr++) {
                    int r = rbase + rr * 8;
                    size_t off = (size_t)r * Hn + nbase + hc;
                    float2 co = *(const float2*)(g_c + off);
                    int q0 = rr * 2, q1 = rr * 2 + 1;
                    float i0 = acc[mt][0 + sub][q0] + bi0, i1 = acc[mt][0 + sub][q1] + bi1;
                    float f0 = acc[mt][2 + sub][q0] + bf0, f1 = acc[mt][2 + sub][q1] + bf1;
                    float gg0 = acc[mt][4 + sub][q0] + bg0, gg1 = acc[mt][4 + sub][q1] + bg1;
                    float o0 = acc[mt][6 + sub][q0] + bo0, o1 = acc[mt][6 + sub][q1] + bo1;
                    float cn0 = sigf(f0) * co.x + sigf(i0) * tanhf_(gg0);
                    float cn1 = sigf(f1) * co.y + sigf(i1) * tanhf_(gg1);
                    *(float2*)(g_c + off) = make_float2(cn0, cn1);
                    __half2 hv = __floats2half2_rn(sigf(o0) * tanhf_(cn0),
                                                   sigf(o1) * tanhf_(cn1));
                    *(__half2*)(hout + off) = hv;
                }
            }
        }

        // grid barrier (sense-reversing)
        __threadfence();
        __syncthreads();
        if (tid == 0) {
            sense ^= 1u;
            unsigned pos = atomicAdd(&g_bar_ctr, 1u);
            if (pos == NGRID - 1) {
                atomicExch(&g_bar_ctr, 0u);
                __threadfence();
                atomicExch(&g_bar_sense, sense);
            } else {
                volatile unsigned* vs = &g_bar_sense;
                while (*vs != sense) __nanosleep(32);
                __threadfence();
            }
        }
        __syncthreads();
    }
}

// ---------------- final FC (t=127 odd -> final h in g_h0) ----------------
__global__ void fc_kernel(const float* __restrict__ w_fc, const float* __restrict__ b_fc,
                          float* __restrict__ out) {
    __shared__ float hs[Hn];
    int b = blockIdx.x;
    const __half2* hsrc = (const __half2*)(g_h0 + (size_t)b * Hn);
    for (int i = threadIdx.x; i < Hn / 2; i += 64) {
        float2 v = __half22float2(hsrc[i]);
        hs[2 * i] = v.x; hs[2 * i + 1] = v.y;
    }
    __syncthreads();
    int o = threadIdx.x;
    const float4* wr = (const float4*)(w_fc + (size_t)o * Hn);
    float acc = 0.0f;
#pragma unroll 8
    for (int k = 0; k < Hn / 4; k++) {
        float4 w4 = wr[k];
        float4 h4 = ((const float4*)hs)[k];
        acc += w4.x * h4.x + w4.y * h4.y + w4.z * h4.z + w4.w * h4.w;
    }
    out[b * On + o] = acc + b_fc[o];
}

extern "C" void kernel_launch(void* const* d_in, const int* in_sizes, int n_in,
                              void* d_out, int out_size) {
    (void)in_sizes; (void)n_in; (void)out_size;
    const float* x    = (const float*)d_in[0];
    const float* w_ih = (const float*)d_in[1];
    const float* w_hh = (const float*)d_in[2];
    const float* b_ih = (const float*)d_in[3];
    const float* b_hh = (const float*)d_in[4];
    const float* w_fc = (const float*)d_in[5];
    const float* b_fc = (const float*)d_in[6];
    float* out = (float*)d_out;

    cudaFuncSetAttribute(lstm_persistent_kernel,
                         cudaFuncAttributeMaxDynamicSharedMemorySize, SMEM_BYTES);

    init_hc_kernel<<<(Bn * Hn) / 256, 256>>>();
    prep_w_kernel<<<(G4 * K_TOT + 255) / 256, 256>>>(w_ih, w_hh);
    prep_x_kernel<<<(Bn * Tn * In) / 256, 256>>>(x);

    dim3 grid(Bn / MT, Hn / HT);   // 8 x 16 = 128 CTAs, all co-resident
    lstm_persistent_kernel<<<grid, 256, SMEM_BYTES>>>(b_ih, b_hh);

    fc_kernel<<<Bn, 64>>>(w_fc, b_fc, out);
}